// round 14
// baseline (speedup 1.0000x reference)
#include <cuda_runtime.h>
#include <math.h>

#define HW 192
#define NPIX (HW*HW)
#define NB 2
#define CIN 180
#define CP 360
#define KDIM 180
#define KP 192            // padded K (12 chunks of 16)
#define MP_PROJ 384       // padded M for proj (6 x 64)
#define MP_FUSE 192       // padded M for fuse (3 x 64)

#define GX 288
#define GY_PROJ 6
#define BLKS_B (GX*GY_PROJ)   // 1728 proj blocks per batch

// ---------------- scratch (static device globals; no allocation) ----------------
__device__ float g_xp[(size_t)NB*CP*NPIX];     // projected (pre-GN) features
__device__ float g_yf[(size_t)NB*CIN*NPIX];    // fused attention output
__device__ float g_part[NB*BLKS_B*4];
__device__ float g_stats[8];                   // [b][g] -> {mu, inv_std}
__device__ float g_affA[NB*CP];                // folded GN scale
__device__ float g_affB[NB*CP];                // folded GN bias
// pre-split tf32 weights, k-major padded: AT[k*MPAD + m]
__device__ float g_ATp_hi[KP*MP_PROJ], g_ATp_lo[KP*MP_PROJ];
__device__ float g_ATf_hi[KP*MP_FUSE], g_ATf_lo[KP*MP_FUSE];

// ---------------- tf32 helpers ----------------
__device__ __forceinline__ void split_tf32(float x, float& hi, float& lo){
  unsigned h; asm("cvt.rna.tf32.f32 %0, %1;" : "=r"(h) : "f"(x));
  float fh = __uint_as_float(h);
  float r = x - fh;
  unsigned l; asm("cvt.rna.tf32.f32 %0, %1;" : "=r"(l) : "f"(r));
  hi = fh; lo = __uint_as_float(l);
}

__device__ __forceinline__ void mma_tf32(float* c, const unsigned* a, const unsigned* b){
  asm volatile(
    "mma.sync.aligned.m16n8k8.row.col.f32.tf32.tf32.f32 "
    "{%0,%1,%2,%3}, {%4,%5,%6,%7}, {%8,%9}, {%0,%1,%2,%3};"
    : "+f"(c[0]), "+f"(c[1]), "+f"(c[2]), "+f"(c[3])
    : "r"(a[0]), "r"(a[1]), "r"(a[2]), "r"(a[3]), "r"(b[0]), "r"(b[1]));
}

// ---------------- weight pre-split (runs each replay; trivial cost) ----------------
__global__ void split_w_kernel(const float* __restrict__ Wp, const float* __restrict__ Wf)
{
  int i = blockIdx.x*256 + threadIdx.x;
  const int NP = KP*MP_PROJ;
  if (i < NP){
    int k = i / MP_PROJ, m = i - k*MP_PROJ;
    float v = (m < CP && k < KDIM) ? Wp[m*KDIM + k] : 0.f;
    float h, l; split_tf32(v, h, l);
    g_ATp_hi[i] = h; g_ATp_lo[i] = l;
  } else {
    int j = i - NP;
    if (j < KP*MP_FUSE){
      int k = j / MP_FUSE, m = j - k*MP_FUSE;
      float v = (m < CIN && k < KDIM) ? Wf[m*KDIM + k] : 0.f;
      float h, l; split_tf32(v, h, l);
      g_ATf_hi[j] = h; g_ATf_lo[j] = l;
    }
  }
}

// ---------------- TF32 GEMM: C[b] = W (MxK) @ X[b] (KxNPIX) + bias ----------------
// BM=64, BN=128, BK=16, 256 threads (8 warps as 2x4), warp tile 32x32.
// 3xTF32 split: C += Ah*Bh + Ah*Bl + Al*Bh  (near-fp32 accuracy).
// PROJ=true : X = input x, C = g_xp, also emit GroupNorm partial sums.
// PROJ=false: X = g_yf,    C = d_out (y).
template<bool PROJ>
__global__ void __launch_bounds__(256) gemm_tf32(const float* __restrict__ Xin,
                                                 const float* __restrict__ bias,
                                                 float* __restrict__ Cout)
{
  constexpr int MPAD = PROJ ? MP_PROJ : MP_FUSE;
  constexpr int M    = PROJ ? CP : CIN;
  const float* AThi = PROJ ? g_ATp_hi : g_ATf_hi;
  const float* ATlo = PROJ ? g_ATp_lo : g_ATf_lo;

  __shared__ float As_hi[16*72],  As_lo[16*72];     // [k][m], stride 72 -> conflict-free
  __shared__ float Bs_hi[16*136], Bs_lo[16*136];    // [k][n], stride 136 -> conflict-free
  __shared__ float red[1024];

  const int b = blockIdx.z;
  const float* X = PROJ ? (Xin + (size_t)b*KDIM*NPIX)
                        : (g_yf + (size_t)b*CIN*NPIX);
  float* C = PROJ ? (g_xp + (size_t)b*CP*NPIX)
                  : (Cout + (size_t)b*CIN*NPIX);

  const int tid  = threadIdx.x;
  const int lane = tid & 31, warp = tid >> 5;
  const int wm = warp >> 2, wn = warp & 3;          // 2 x 4 warp grid
  const int g  = lane >> 2, t = lane & 3;
  const int m0 = blockIdx.y*64, n0 = blockIdx.x*128;

  float Cf[2][4][4];
#pragma unroll
  for (int mi=0;mi<2;mi++)
#pragma unroll
    for (int ni=0;ni<4;ni++)
#pragma unroll
      for (int e=0;e<4;e++) Cf[mi][ni][e] = 0.f;

  for (int k0 = 0; k0 < KP; k0 += 16){
    // --- A tile (pre-split, zero-padded, coalesced in m) ---
#pragma unroll
    for (int l=0;l<4;l++){
      int idx = l*256 + tid;
      int kk = idx >> 6, m = idx & 63;
      int src = (k0+kk)*MPAD + m0 + m;
      As_hi[kk*72 + m] = AThi[src];
      As_lo[kk*72 + m] = ATlo[src];
    }
    // --- B tile (fp32 load, split on the fly, float4 both ways) ---
#pragma unroll
    for (int l=0;l<2;l++){
      int idx = l*256 + tid;
      int kk = idx >> 5, c4 = idx & 31;
      int gk = k0 + kk;
      float4 v = make_float4(0.f,0.f,0.f,0.f);
      if (gk < KDIM) v = *(const float4*)(X + (size_t)gk*NPIX + n0 + c4*4);
      float4 h4, l4;
      split_tf32(v.x, h4.x, l4.x); split_tf32(v.y, h4.y, l4.y);
      split_tf32(v.z, h4.z, l4.z); split_tf32(v.w, h4.w, l4.w);
      *(float4*)(Bs_hi + kk*136 + c4*4) = h4;
      *(float4*)(Bs_lo + kk*136 + c4*4) = l4;
    }
    __syncthreads();

#pragma unroll
    for (int ks=0; ks<2; ks++){
      const int kb = ks*8;
      unsigned Ah[2][4], Al[2][4], Bh[4][2], Bl[4][2];
#pragma unroll
      for (int mi=0;mi<2;mi++){
        int r = wm*32 + mi*16 + g;
        Ah[mi][0] = __float_as_uint(As_hi[(kb+t  )*72 + r    ]);
        Ah[mi][1] = __float_as_uint(As_hi[(kb+t  )*72 + r + 8]);
        Ah[mi][2] = __float_as_uint(As_hi[(kb+t+4)*72 + r    ]);
        Ah[mi][3] = __float_as_uint(As_hi[(kb+t+4)*72 + r + 8]);
        Al[mi][0] = __float_as_uint(As_lo[(kb+t  )*72 + r    ]);
        Al[mi][1] = __float_as_uint(As_lo[(kb+t  )*72 + r + 8]);
        Al[mi][2] = __float_as_uint(As_lo[(kb+t+4)*72 + r    ]);
        Al[mi][3] = __float_as_uint(As_lo[(kb+t+4)*72 + r + 8]);
      }
#pragma unroll
      for (int ni=0;ni<4;ni++){
        int c = wn*32 + ni*8 + g;
        Bh[ni][0] = __float_as_uint(Bs_hi[(kb+t  )*136 + c]);
        Bh[ni][1] = __float_as_uint(Bs_hi[(kb+t+4)*136 + c]);
        Bl[ni][0] = __float_as_uint(Bs_lo[(kb+t  )*136 + c]);
        Bl[ni][1] = __float_as_uint(Bs_lo[(kb+t+4)*136 + c]);
      }
#pragma unroll
      for (int mi=0;mi<2;mi++)
#pragma unroll
        for (int ni=0;ni<4;ni++){
          mma_tf32(Cf[mi][ni], Ah[mi], Bh[ni]);
          mma_tf32(Cf[mi][ni], Ah[mi], Bl[ni]);
          mma_tf32(Cf[mi][ni], Al[mi], Bh[ni]);
        }
    }
    __syncthreads();
  }

  // --- epilogue: bias add, store, GN partial sums (PROJ) ---
  float st0=0.f, st1=0.f, st2=0.f, st3=0.f;
#pragma unroll
  for (int mi=0;mi<2;mi++){
#pragma unroll
    for (int rs=0;rs<2;rs++){
      int gm = m0 + wm*32 + mi*16 + g + rs*8;
      if (gm < M){
        float bb = bias[gm];
        float* crow = C + (size_t)gm*NPIX + n0 + wn*32;
        float s = 0.f, q = 0.f;
#pragma unroll
        for (int ni=0;ni<4;ni++){
          float v0 = Cf[mi][ni][rs*2+0] + bb;
          float v1 = Cf[mi][ni][rs*2+1] + bb;
          *(float2*)(crow + ni*8 + 2*t) = make_float2(v0, v1);
          if (PROJ){ s += v0 + v1; q = fmaf(v0,v0,fmaf(v1,v1,q)); }
        }
        if (PROJ){
          if (gm < CIN){ st0 += s; st1 += q; } else { st2 += s; st3 += q; }
        }
      }
    }
  }
  if (PROJ){
    __syncthreads();
    red[tid] = st0; red[256+tid] = st1; red[512+tid] = st2; red[768+tid] = st3;
    __syncthreads();
    for (int o=128;o;o>>=1){
      if (tid < o){
        red[tid]     += red[tid+o];
        red[256+tid] += red[256+tid+o];
        red[512+tid] += red[512+tid+o];
        red[768+tid] += red[768+tid+o];
      }
      __syncthreads();
    }
    if (tid == 0){
      int bid = (blockIdx.z*gridDim.y + blockIdx.y)*gridDim.x + blockIdx.x;
      g_part[bid*4+0]=red[0];   g_part[bid*4+1]=red[256];
      g_part[bid*4+2]=red[512]; g_part[bid*4+3]=red[768];
    }
  }
}

// ---------------- GroupNorm stats: deterministic reduce of partials ----------------
__global__ void stats_kernel()
{
  const int bg = blockIdx.x;          // b*2 + g, 4 blocks
  const int b = bg >> 1, g = bg & 1;
  __shared__ float ss[256], sq[256];
  float s = 0.f, q = 0.f;
  for (int i = threadIdx.x; i < BLKS_B; i += 256){
    int bid = b*BLKS_B + i;
    s += g_part[bid*4 + g*2];
    q += g_part[bid*4 + g*2 + 1];
  }
  ss[threadIdx.x] = s; sq[threadIdx.x] = q;
  __syncthreads();
  for (int o=128;o;o>>=1){
    if (threadIdx.x < o){ ss[threadIdx.x]+=ss[threadIdx.x+o]; sq[threadIdx.x]+=sq[threadIdx.x+o]; }
    __syncthreads();
  }
  if (threadIdx.x == 0){
    const float N = 180.f * (float)NPIX;
    float mu  = ss[0] / N;
    float var = sq[0] / N - mu*mu;
    g_stats[bg*2]   = mu;
    g_stats[bg*2+1] = rsqrtf(var + 1e-5f);
  }
}

// Fold GN into per-(batch,channel) affine: xn = xp * A + B
__global__ void affine_kernel(const float* __restrict__ gamma, const float* __restrict__ beta)
{
  int i = blockIdx.x*256 + threadIdx.x;
  if (i < NB*CP){
    int c = i % CP, b = i / CP;
    int g = (c >= CIN) ? 1 : 0;
    float mu   = g_stats[(b*2+g)*2];
    float istd = g_stats[(b*2+g)*2+1];
    float a = istd * gamma[c];
    g_affA[i] = a;
    g_affB[i] = fmaf(-mu, a, beta[c]);
  }
}

// ---------------- windowed attention, one block per (window, head) ----------------
// The reference's "global token" path is an exact identity (softmax of selected
// rows == selected rows of softmax), so attn maps and outputs are plain local
// window attention. Writes softmax rows to attn_out (= d_out slice) and
// scale_w * (attn@V) directly into g_yf.
template<int WS, int HE, int CHN, int NCH>
__global__ void __launch_bounds__(256) attn_kernel(int branch,
                                                   const float* __restrict__ swp,
                                                   float* __restrict__ attn_out)
{
  constexpr int T    = WS*WS;
  constexpr int NWIN = HW/WS;
  constexpr int TPAD = T + 4;
  constexpr int CPC  = CHN / NCH;
  static_assert(CHN % NCH == 0, "chunking");

  extern __shared__ float sm[];
  float* qT = sm;                  // [CHN][T]  (already *he^-0.5, GN applied)
  float* vT = sm + CHN*T;          // [CHN][T]
  float* Am = sm + 2*CHN*T;        // [T][TPAD]
  __shared__ int pixs[T];

  const int w  = blockIdx.x;
  const int hh = blockIdx.y;
  const int b  = w / (NWIN*NWIN);
  const int r  = w - b*NWIN*NWIN;
  const int ih = r / NWIN, iw = r - ih*NWIN;
  const int tid = threadIdx.x;

  if (tid < T){
    int ty = tid / WS, tx = tid - ty*WS;
    int hs  = (ih*WS + ty - WS/2 + HW) % HW;   // roll(+ws/2) on H
    int wsr = (iw*WS + tx + WS/2) % HW;        // roll(-ws/2) on W
    pixs[tid] = hs*HW + wsr;                   // same pixel for gather & scatter
  }
  __syncthreads();

  const float qsc = (HE==2) ? 0.70710678f : (HE==4) ? 0.5f : 0.40824829f;
  const float* xp = g_xp + (size_t)b*CP*NPIX;
  const float* aA = g_affA + b*CP;
  const float* aB = g_affB + b*CP;
  const int cb = branch*120 + hh;             // q channel = cb + cc*HE ; v = +60

  // ---- load + GN-normalize Q,V ----
  for (int idx = tid; idx < CHN*T; idx += 256){
    int cc = idx / T, t = idx - cc*T;
    int pix = pixs[t];
    int Cq = cb + cc*HE;
    int Cv = Cq + 60;
    float q = xp[(size_t)Cq*NPIX + pix];
    float v = xp[(size_t)Cv*NPIX + pix];
    qT[idx] = fmaf(q, aA[Cq], aB[Cq]) * qsc;
    vT[idx] = fmaf(v, aA[Cv], aB[Cv]);
  }
  __syncthreads();

  // ---- S = (q_l)(q_l)^T  (4x4 register tiles) ----
  constexpr int NT4 = T/4;
  for (int tile = tid; tile < NT4*NT4; tile += 256){
    int tt = tile / NT4, ssi = tile - tt*NT4;
    int t0 = tt*4, s0 = ssi*4;
    float accv[4][4];
#pragma unroll
    for (int i=0;i<4;i++)
#pragma unroll
      for (int j=0;j<4;j++) accv[i][j] = 0.f;
#pragma unroll
    for (int c=0;c<CHN;c++){
      float4 qa = *(const float4*)(qT + c*T + t0);
      float4 qb = *(const float4*)(qT + c*T + s0);
      float qav[4] = {qa.x,qa.y,qa.z,qa.w};
      float qbv[4] = {qb.x,qb.y,qb.z,qb.w};
#pragma unroll
      for (int i=0;i<4;i++)
#pragma unroll
        for (int j=0;j<4;j++)
          accv[i][j] = fmaf(qav[i], qbv[j], accv[i][j]);
    }
#pragma unroll
    for (int i=0;i<4;i++)
      *(float4*)(Am + (t0+i)*TPAD + s0) =
          make_float4(accv[i][0],accv[i][1],accv[i][2],accv[i][3]);
  }
  __syncthreads();

  // ---- softmax per row + write attn map to global ----
  const int warp = tid >> 5, lane = tid & 31;
  for (int t = warp; t < T; t += 8){
    float* arow = Am + t*TPAD;
    float mx = -1e30f;
    for (int s=lane; s<T; s+=32) mx = fmaxf(mx, arow[s]);
#pragma unroll
    for (int o=16;o;o>>=1) mx = fmaxf(mx, __shfl_xor_sync(0xffffffffu, mx, o));
    float sum = 0.f;
    for (int s=lane; s<T; s+=32){ float e = __expf(arow[s]-mx); arow[s]=e; sum+=e; }
#pragma unroll
    for (int o=16;o;o>>=1) sum += __shfl_xor_sync(0xffffffffu, sum, o);
    float inv = 1.f/sum;
    float* grow = attn_out + (((size_t)w*HE + hh)*T + t)*T;
    for (int s=lane; s<T; s+=32){ float p = arow[s]*inv; arow[s]=p; grow[s]=p; }
  }
  __syncthreads();

  // ---- O = attn @ V, scatter scaled output into y_fused ----
  float sw = swp[branch];
  if (tid < T*NCH){
    int chunk = tid / T, t = tid - chunk*T;
    const float* arow = Am + t*TPAD;
    const float* vb = vT + chunk*CPC*T;
    float o[CPC];
#pragma unroll
    for (int c=0;c<CPC;c++) o[c] = 0.f;
    for (int s=0; s<T; s+=4){
      float4 a4 = *(const float4*)(arow + s);
#pragma unroll
      for (int c=0;c<CPC;c++){
        float4 v4 = *(const float4*)(vb + c*T + s);
        o[c] = fmaf(a4.x, v4.x, o[c]);
        o[c] = fmaf(a4.y, v4.y, o[c]);
        o[c] = fmaf(a4.z, v4.z, o[c]);
        o[c] = fmaf(a4.w, v4.w, o[c]);
      }
    }
    int pix = pixs[t];
    float* yb = g_yf + (size_t)b*CIN*NPIX;
#pragma unroll
    for (int c=0;c<CPC;c++){
      int cc = chunk*CPC + c;
      int Cy = branch*60 + cc*HE + hh;
      yb[(size_t)Cy*NPIX + pix] = sw * o[c];
    }
  }
}

// ---------------- launcher ----------------
extern "C" void kernel_launch(void* const* d_in, const int* in_sizes, int n_in,
                              void* d_out, int out_size)
{
  const float* x        = (const float*)d_in[0];
  const float* proj_w   = (const float*)d_in[1];
  const float* proj_b   = (const float*)d_in[2];
  const float* gn_gamma = (const float*)d_in[3];
  const float* gn_beta  = (const float*)d_in[4];
  // d_in[5] token_scores: provably unused (global path is identity)
  const float* scale_w  = (const float*)d_in[6];
  const float* fuse_w   = (const float*)d_in[7];
  const float* fuse_b   = (const float*)d_in[8];
  float* out = (float*)d_out;

  // d_out layout: y | atn0 | atn1 | atn2
  const size_t OFF_A0 = (size_t)NB*CIN*NPIX;
  const size_t OFF_A1 = OFF_A0 + (size_t)NB*48*48*2*16*16;
  const size_t OFF_A2 = OFF_A1 + (size_t)NB*24*24*4*64*64;

  const int SM0 = (2*30*16  + 16*20)  * 4;   //  5,120 B
  const int SM1 = (2*15*64  + 64*68)  * 4;   // 25,088 B
  const int SM2 = (2*10*144 + 144*148)* 4;   // 96,768 B
  cudaFuncSetAttribute(attn_kernel<12,6,10,1>,
                       cudaFuncAttributeMaxDynamicSharedMemorySize, SM2);

  // 0) pre-split weights into tf32 hi/lo (padded, k-major)
  int prep_n = KP*MP_PROJ + KP*MP_FUSE;
  split_w_kernel<<<(prep_n + 255)/256, 256>>>(proj_w, fuse_w);
  // 1) proj GEMM (tensor core) + GN partials
  gemm_tf32<true><<<dim3(GX, GY_PROJ, NB), 256>>>(x, proj_b, nullptr);
  // 2) GN stats + affine fold
  stats_kernel<<<4, 256>>>();
  affine_kernel<<<3, 256>>>(gn_gamma, gn_beta);
  // 3) three attention branches
  attn_kernel<4, 2, 30, 15><<<dim3(NB*48*48, 2), 256, SM0>>>(0, scale_w, out + OFF_A0);
  attn_kernel<8, 4, 15,  3><<<dim3(NB*24*24, 4), 256, SM1>>>(1, scale_w, out + OFF_A1);
  attn_kernel<12,6, 10,  1><<<dim3(NB*16*16, 6), 256, SM2>>>(2, scale_w, out + OFF_A2);
  // 4) fuse GEMM (tensor core) -> y
  gemm_tf32<false><<<dim3(GX, 3, NB), 256>>>(nullptr, fuse_b, out);
}

// round 15
// speedup vs baseline: 1.0325x; 1.0325x over previous
#include <cuda_runtime.h>
#include <math.h>

#define HW 192
#define NPIX (HW*HW)
#define NB 2
#define CIN 180
#define CP 360
#define KDIM 180
#define KP 192            // padded K (24 chunks of 8)
#define MP_PROJ 384       // padded M for proj (24 tiles of 16)
#define MP_FUSE 192       // padded M for fuse (12 tiles of 16)

#define GX 288
#define GY_PROJ 6
#define BLKS_B (GX*GY_PROJ)   // 1728 proj blocks per batch

#define BSTRIDE 136       // B smem row stride (banks: g + 8t + c0 -> all 32)

// ---------------- scratch (static device globals; no allocation) ----------------
__device__ float g_xp[(size_t)NB*CP*NPIX];     // projected (pre-GN) features
__device__ float g_yf[(size_t)NB*CIN*NPIX];    // fused attention output
__device__ float g_part[NB*BLKS_B*4];
__device__ float g_affA[NB*CP];                // folded GN scale
__device__ float g_affB[NB*CP];                // folded GN bias
// A (=W^T) in tf32 hi/lo, stored in m16n8k8 FRAGMENT order:
// frag = kc*(MPAD/16)+mt ; float index = frag*128 + lane*4 + j
// value = W[mt*16 + g + (j&1)*8 ,  kc*8 + t + (j>>1)*4],  g=lane>>2, t=lane&3
__device__ float g_ATp_hi[KP*MP_PROJ], g_ATp_lo[KP*MP_PROJ];
__device__ float g_ATf_hi[KP*MP_FUSE], g_ATf_lo[KP*MP_FUSE];

// ---------------- tf32 helpers ----------------
__device__ __forceinline__ void split_tf32(float x, float& hi, float& lo){
  unsigned h; asm("cvt.rna.tf32.f32 %0, %1;" : "=r"(h) : "f"(x));
  float fh = __uint_as_float(h);
  float r = x - fh;
  unsigned l; asm("cvt.rna.tf32.f32 %0, %1;" : "=r"(l) : "f"(r));
  hi = fh; lo = __uint_as_float(l);
}

__device__ __forceinline__ void mma_tf32(float* c, const float4 a, const unsigned* b){
  asm volatile(
    "mma.sync.aligned.m16n8k8.row.col.f32.tf32.tf32.f32 "
    "{%0,%1,%2,%3}, {%4,%5,%6,%7}, {%8,%9}, {%0,%1,%2,%3};"
    : "+f"(c[0]), "+f"(c[1]), "+f"(c[2]), "+f"(c[3])
    : "r"(__float_as_uint(a.x)), "r"(__float_as_uint(a.y)),
      "r"(__float_as_uint(a.z)), "r"(__float_as_uint(a.w)),
      "r"(b[0]), "r"(b[1]));
}

// ---------------- weight pre-split into fragment layout ----------------
__global__ void split_w_kernel(const float* __restrict__ Wp, const float* __restrict__ Wf)
{
  int i = blockIdx.x*256 + threadIdx.x;
  const int NP = KP*MP_PROJ;
  if (i < NP){
    int j = i & 3, lane = (i >> 2) & 31, frag = i >> 7;
    int mt = frag % (MP_PROJ/16), kc = frag / (MP_PROJ/16);
    int g = lane >> 2, t = lane & 3;
    int row = mt*16 + g + (j & 1)*8;
    int k   = kc*8  + t + (j >> 1)*4;
    float v = (row < CP && k < KDIM) ? Wp[row*KDIM + k] : 0.f;
    float h, l; split_tf32(v, h, l);
    g_ATp_hi[i] = h; g_ATp_lo[i] = l;
  } else {
    int i2 = i - NP;
    if (i2 < KP*MP_FUSE){
      int j = i2 & 3, lane = (i2 >> 2) & 31, frag = i2 >> 7;
      int mt = frag % (MP_FUSE/16), kc = frag / (MP_FUSE/16);
      int g = lane >> 2, t = lane & 3;
      int row = mt*16 + g + (j & 1)*8;
      int k   = kc*8  + t + (j >> 1)*4;
      float v = (row < CIN && k < KDIM) ? Wf[row*KDIM + k] : 0.f;
      float h, l; split_tf32(v, h, l);
      g_ATf_hi[i2] = h; g_ATf_lo[i2] = l;
    }
  }
}

// ---------------- TF32 GEMM: C[b] = W (MxK) @ X[b] (KxNPIX) + bias ----------------
// BM=64, BN=128, BK=16. 256 threads, 2x4 warp grid, 32x32 warp tiles.
// A fragments come straight from global (fragment-ordered, L1/L2-hot).
// B is split on the fly into k-major smem rows (stride 136, conflict-free).
// 3xTF32: C += Ah*Bh + Ah*Bl + Al*Bh.
template<bool PROJ>
__global__ void __launch_bounds__(256) gemm_tf32(const float* __restrict__ Xin,
                                                 const float* __restrict__ bias,
                                                 float* __restrict__ Cout)
{
  constexpr int MPAD = PROJ ? MP_PROJ : MP_FUSE;
  constexpr int MT   = MPAD/16;
  constexpr int M    = PROJ ? CP : CIN;
  const float4* Afh = (const float4*)(PROJ ? g_ATp_hi : g_ATf_hi);
  const float4* Afl = (const float4*)(PROJ ? g_ATp_lo : g_ATf_lo);

  __shared__ float Bs_hi[16*BSTRIDE], Bs_lo[16*BSTRIDE];
  __shared__ float red[1024];

  const int b = blockIdx.z;
  const float* X = PROJ ? (Xin + (size_t)b*KDIM*NPIX)
                        : (g_yf + (size_t)b*CIN*NPIX);
  float* C = PROJ ? (g_xp + (size_t)b*CP*NPIX)
                  : (Cout + (size_t)b*CIN*NPIX);

  const int tid  = threadIdx.x;
  const int lane = tid & 31, warp = tid >> 5;
  const int wm = warp >> 2, wn = warp & 3;          // 2 x 4 warp grid
  const int g  = lane >> 2, t = lane & 3;
  const int m0 = blockIdx.y*64, n0 = blockIdx.x*128;

  // B loader coords (fixed per thread): two float4 rows per 16-k chunk
  const int kk0 = tid >> 5,  c40 = (tid & 31);          // l=0: k row 0..7
  const int kk1 = (256+tid) >> 5, c41 = (tid & 31);     // l=1: k row 8..15

  float Cf[2][4][4];
#pragma unroll
  for (int mi=0;mi<2;mi++)
#pragma unroll
    for (int ni=0;ni<4;ni++)
#pragma unroll
      for (int e=0;e<4;e++) Cf[mi][ni][e] = 0.f;

  // prefetch chunk 0 (raw fp32)
  float4 v0 = (kk0 < KDIM) ? *(const float4*)(X + (size_t)kk0*NPIX + n0 + c40*4)
                           : make_float4(0,0,0,0);
  float4 v1 = (kk1 < KDIM) ? *(const float4*)(X + (size_t)kk1*NPIX + n0 + c41*4)
                           : make_float4(0,0,0,0);

  for (int ki = 0; ki < 12; ki++){
    // split + store current chunk to smem
    {
      float4 h4, l4;
      split_tf32(v0.x,h4.x,l4.x); split_tf32(v0.y,h4.y,l4.y);
      split_tf32(v0.z,h4.z,l4.z); split_tf32(v0.w,h4.w,l4.w);
      *(float4*)(Bs_hi + kk0*BSTRIDE + c40*4) = h4;
      *(float4*)(Bs_lo + kk0*BSTRIDE + c40*4) = l4;
      split_tf32(v1.x,h4.x,l4.x); split_tf32(v1.y,h4.y,l4.y);
      split_tf32(v1.z,h4.z,l4.z); split_tf32(v1.w,h4.w,l4.w);
      *(float4*)(Bs_hi + kk1*BSTRIDE + c41*4) = h4;
      *(float4*)(Bs_lo + kk1*BSTRIDE + c41*4) = l4;
    }
    __syncthreads();
    // prefetch next chunk
    if (ki < 11){
      int gk0 = (ki+1)*16 + kk0, gk1 = (ki+1)*16 + kk1;
      v0 = (gk0 < KDIM) ? *(const float4*)(X + (size_t)gk0*NPIX + n0 + c40*4)
                        : make_float4(0,0,0,0);
      v1 = (gk1 < KDIM) ? *(const float4*)(X + (size_t)gk1*NPIX + n0 + c41*4)
                        : make_float4(0,0,0,0);
    }
    // compute on current chunk
#pragma unroll
    for (int ks=0; ks<2; ks++){
      const int kc = ki*2 + ks;
      float4 Ah[2], Al[2];
#pragma unroll
      for (int mi=0;mi<2;mi++){
        int mt = (m0>>4) + wm*2 + mi;
        int fo = (kc*MT + mt)*32 + lane;
        Ah[mi] = Afh[fo];
        Al[mi] = Afl[fo];
      }
      unsigned Bh[4][2], Bl[4][2];
#pragma unroll
      for (int ni=0;ni<4;ni++){
        int c = wn*32 + ni*8 + g;
        Bh[ni][0] = __float_as_uint(Bs_hi[(ks*8+t  )*BSTRIDE + c]);
        Bh[ni][1] = __float_as_uint(Bs_hi[(ks*8+t+4)*BSTRIDE + c]);
        Bl[ni][0] = __float_as_uint(Bs_lo[(ks*8+t  )*BSTRIDE + c]);
        Bl[ni][1] = __float_as_uint(Bs_lo[(ks*8+t+4)*BSTRIDE + c]);
      }
#pragma unroll
      for (int mi=0;mi<2;mi++)
#pragma unroll
        for (int ni=0;ni<4;ni++){
          mma_tf32(Cf[mi][ni], Ah[mi], Bh[ni]);
          mma_tf32(Cf[mi][ni], Ah[mi], Bl[ni]);
          mma_tf32(Cf[mi][ni], Al[mi], Bh[ni]);
        }
    }
    __syncthreads();
  }

  // --- epilogue: bias add, store, GN partial sums (PROJ) ---
  float st0=0.f, st1=0.f, st2=0.f, st3=0.f;
#pragma unroll
  for (int mi=0;mi<2;mi++){
#pragma unroll
    for (int rs=0;rs<2;rs++){
      int gm = m0 + wm*32 + mi*16 + g + rs*8;
      if (gm < M){
        float bb = bias[gm];
        float* crow = C + (size_t)gm*NPIX + n0 + wn*32;
        float s = 0.f, q = 0.f;
#pragma unroll
        for (int ni=0;ni<4;ni++){
          float u0 = Cf[mi][ni][rs*2+0] + bb;
          float u1 = Cf[mi][ni][rs*2+1] + bb;
          *(float2*)(crow + ni*8 + 2*t) = make_float2(u0, u1);
          if (PROJ){ s += u0 + u1; q = fmaf(u0,u0,fmaf(u1,u1,q)); }
        }
        if (PROJ){
          if (gm < CIN){ st0 += s; st1 += q; } else { st2 += s; st3 += q; }
        }
      }
    }
  }
  if (PROJ){
    __syncthreads();
    red[tid] = st0; red[256+tid] = st1; red[512+tid] = st2; red[768+tid] = st3;
    __syncthreads();
    for (int o=128;o;o>>=1){
      if (tid < o){
        red[tid]     += red[tid+o];
        red[256+tid] += red[256+tid+o];
        red[512+tid] += red[512+tid+o];
        red[768+tid] += red[768+tid+o];
      }
      __syncthreads();
    }
    if (tid == 0){
      int bid = (blockIdx.z*gridDim.y + blockIdx.y)*gridDim.x + blockIdx.x;
      g_part[bid*4+0]=red[0];   g_part[bid*4+1]=red[256];
      g_part[bid*4+2]=red[512]; g_part[bid*4+3]=red[768];
    }
  }
}

// ---------------- GN stats + affine fold (single block, deterministic) ----------------
__global__ void stats_affine_kernel(const float* __restrict__ gamma,
                                    const float* __restrict__ beta)
{
  __shared__ float ss[256], sq[256];
  __shared__ float stats[8];
  const int tid = threadIdx.x;
  for (int bg = 0; bg < 4; bg++){
    const int b = bg >> 1, gg = bg & 1;
    float s = 0.f, q = 0.f;
    for (int i = tid; i < BLKS_B; i += 256){
      int bid = b*BLKS_B + i;
      s += g_part[bid*4 + gg*2];
      q += g_part[bid*4 + gg*2 + 1];
    }
    ss[tid] = s; sq[tid] = q;
    __syncthreads();
    for (int o=128;o;o>>=1){
      if (tid < o){ ss[tid]+=ss[tid+o]; sq[tid]+=sq[tid+o]; }
      __syncthreads();
    }
    if (tid == 0){
      const float N = 180.f * (float)NPIX;
      float mu  = ss[0] / N;
      float var = sq[0] / N - mu*mu;
      stats[bg*2]   = mu;
      stats[bg*2+1] = rsqrtf(var + 1e-5f);
    }
    __syncthreads();
  }
  for (int i = tid; i < NB*CP; i += 256){
    int c = i % CP, b = i / CP;
    int gg = (c >= CIN) ? 1 : 0;
    float mu   = stats[(b*2+gg)*2];
    float istd = stats[(b*2+gg)*2+1];
    float a = istd * gamma[c];
    g_affA[i] = a;
    g_affB[i] = fmaf(-mu, a, beta[c]);
  }
}

// ---------------- windowed attention, one block per (window, head) ----------------
// The reference's "global token" path is an exact identity (softmax of selected
// rows == selected rows of softmax), so attn maps and outputs are plain local
// window attention. Writes softmax rows to attn_out (= d_out slice) and
// scale_w * (attn@V) directly into g_yf.
template<int WS, int HE, int CHN, int NCH>
__global__ void __launch_bounds__(256) attn_kernel(int branch,
                                                   const float* __restrict__ swp,
                                                   float* __restrict__ attn_out)
{
  constexpr int T    = WS*WS;
  constexpr int NWIN = HW/WS;
  constexpr int TPAD = T + 4;
  constexpr int CPC  = CHN / NCH;
  static_assert(CHN % NCH == 0, "chunking");

  extern __shared__ float sm[];
  float* qT = sm;                  // [CHN][T]  (already *he^-0.5, GN applied)
  float* vT = sm + CHN*T;          // [CHN][T]
  float* Am = sm + 2*CHN*T;        // [T][TPAD]
  __shared__ int pixs[T];

  const int w  = blockIdx.x;
  const int hh = blockIdx.y;
  const int b  = w / (NWIN*NWIN);
  const int r  = w - b*NWIN*NWIN;
  const int ih = r / NWIN, iw = r - ih*NWIN;
  const int tid = threadIdx.x;

  if (tid < T){
    int ty = tid / WS, tx = tid - ty*WS;
    int hs  = (ih*WS + ty - WS/2 + HW) % HW;   // roll(+ws/2) on H
    int wsr = (iw*WS + tx + WS/2) % HW;        // roll(-ws/2) on W
    pixs[tid] = hs*HW + wsr;                   // same pixel for gather & scatter
  }
  __syncthreads();

  const float qsc = (HE==2) ? 0.70710678f : (HE==4) ? 0.5f : 0.40824829f;
  const float* xp = g_xp + (size_t)b*CP*NPIX;
  const float* aA = g_affA + b*CP;
  const float* aB = g_affB + b*CP;
  const int cb = branch*120 + hh;             // q channel = cb + cc*HE ; v = +60

  // ---- load + GN-normalize Q,V ----
  for (int idx = tid; idx < CHN*T; idx += 256){
    int cc = idx / T, t = idx - cc*T;
    int pix = pixs[t];
    int Cq = cb + cc*HE;
    int Cv = Cq + 60;
    float q = xp[(size_t)Cq*NPIX + pix];
    float v = xp[(size_t)Cv*NPIX + pix];
    qT[idx] = fmaf(q, aA[Cq], aB[Cq]) * qsc;
    vT[idx] = fmaf(v, aA[Cv], aB[Cv]);
  }
  __syncthreads();

  // ---- S = (q_l)(q_l)^T  (4x4 register tiles) ----
  constexpr int NT4 = T/4;
  for (int tile = tid; tile < NT4*NT4; tile += 256){
    int tt = tile / NT4, ssi = tile - tt*NT4;
    int t0 = tt*4, s0 = ssi*4;
    float accv[4][4];
#pragma unroll
    for (int i=0;i<4;i++)
#pragma unroll
      for (int j=0;j<4;j++) accv[i][j] = 0.f;
#pragma unroll
    for (int c=0;c<CHN;c++){
      float4 qa = *(const float4*)(qT + c*T + t0);
      float4 qb = *(const float4*)(qT + c*T + s0);
      float qav[4] = {qa.x,qa.y,qa.z,qa.w};
      float qbv[4] = {qb.x,qb.y,qb.z,qb.w};
#pragma unroll
      for (int i=0;i<4;i++)
#pragma unroll
        for (int j=0;j<4;j++)
          accv[i][j] = fmaf(qav[i], qbv[j], accv[i][j]);
    }
#pragma unroll
    for (int i=0;i<4;i++)
      *(float4*)(Am + (t0+i)*TPAD + s0) =
          make_float4(accv[i][0],accv[i][1],accv[i][2],accv[i][3]);
  }
  __syncthreads();

  // ---- softmax per row + write attn map to global ----
  const int warp = tid >> 5, lane = tid & 31;
  for (int t = warp; t < T; t += 8){
    float* arow = Am + t*TPAD;
    float mx = -1e30f;
    for (int s=lane; s<T; s+=32) mx = fmaxf(mx, arow[s]);
#pragma unroll
    for (int o=16;o;o>>=1) mx = fmaxf(mx, __shfl_xor_sync(0xffffffffu, mx, o));
    float sum = 0.f;
    for (int s=lane; s<T; s+=32){ float e = __expf(arow[s]-mx); arow[s]=e; sum+=e; }
#pragma unroll
    for (int o=16;o;o>>=1) sum += __shfl_xor_sync(0xffffffffu, sum, o);
    float inv = 1.f/sum;
    float* grow = attn_out + (((size_t)w*HE + hh)*T + t)*T;
    for (int s=lane; s<T; s+=32){ float p = arow[s]*inv; arow[s]=p; grow[s]=p; }
  }
  __syncthreads();

  // ---- O = attn @ V, scatter scaled output into y_fused ----
  float sw = swp[branch];
  if (tid < T*NCH){
    int chunk = tid / T, t = tid - chunk*T;
    const float* arow = Am + t*TPAD;
    const float* vb = vT + chunk*CPC*T;
    float o[CPC];
#pragma unroll
    for (int c=0;c<CPC;c++) o[c] = 0.f;
    for (int s=0; s<T; s+=4){
      float4 a4 = *(const float4*)(arow + s);
#pragma unroll
      for (int c=0;c<CPC;c++){
        float4 v4 = *(const float4*)(vb + c*T + s);
        o[c] = fmaf(a4.x, v4.x, o[c]);
        o[c] = fmaf(a4.y, v4.y, o[c]);
        o[c] = fmaf(a4.z, v4.z, o[c]);
        o[c] = fmaf(a4.w, v4.w, o[c]);
      }
    }
    int pix = pixs[t];
    float* yb = g_yf + (size_t)b*CIN*NPIX;
#pragma unroll
    for (int c=0;c<CPC;c++){
      int cc = chunk*CPC + c;
      int Cy = branch*60 + cc*HE + hh;
      yb[(size_t)Cy*NPIX + pix] = sw * o[c];
    }
  }
}

// ---------------- launcher ----------------
extern "C" void kernel_launch(void* const* d_in, const int* in_sizes, int n_in,
                              void* d_out, int out_size)
{
  const float* x        = (const float*)d_in[0];
  const float* proj_w   = (const float*)d_in[1];
  const float* proj_b   = (const float*)d_in[2];
  const float* gn_gamma = (const float*)d_in[3];
  const float* gn_beta  = (const float*)d_in[4];
  // d_in[5] token_scores: provably unused (global path is identity)
  const float* scale_w  = (const float*)d_in[6];
  const float* fuse_w   = (const float*)d_in[7];
  const float* fuse_b   = (const float*)d_in[8];
  float* out = (float*)d_out;

  // d_out layout: y | atn0 | atn1 | atn2
  const size_t OFF_A0 = (size_t)NB*CIN*NPIX;
  const size_t OFF_A1 = OFF_A0 + (size_t)NB*48*48*2*16*16;
  const size_t OFF_A2 = OFF_A1 + (size_t)NB*24*24*4*64*64;

  const int SM0 = (2*30*16  + 16*20)  * 4;   //  5,120 B
  const int SM1 = (2*15*64  + 64*68)  * 4;   // 25,088 B
  const int SM2 = (2*10*144 + 144*148)* 4;   // 96,768 B
  cudaFuncSetAttribute(attn_kernel<12,6,10,1>,
                       cudaFuncAttributeMaxDynamicSharedMemorySize, SM2);

  // 0) pre-split weights into tf32 hi/lo fragment layout
  int prep_n = KP*MP_PROJ + KP*MP_FUSE;
  split_w_kernel<<<(prep_n + 255)/256, 256>>>(proj_w, fuse_w);
  // 1) proj GEMM (tensor core) + GN partials
  gemm_tf32<true><<<dim3(GX, GY_PROJ, NB), 256>>>(x, proj_b, nullptr);
  // 2) GN stats + affine fold
  stats_affine_kernel<<<1, 256>>>(gn_gamma, gn_beta);
  // 3) three attention branches
  attn_kernel<4, 2, 30, 15><<<dim3(NB*48*48, 2), 256, SM0>>>(0, scale_w, out + OFF_A0);
  attn_kernel<8, 4, 15,  3><<<dim3(NB*24*24, 4), 256, SM1>>>(1, scale_w, out + OFF_A1);
  attn_kernel<12,6, 10,  1><<<dim3(NB*16*16, 6), 256, SM2>>>(2, scale_w, out + OFF_A2);
  // 4) fuse GEMM (tensor core) -> y
  gemm_tf32<false><<<dim3(GX, 3, NB), 256>>>(nullptr, fuse_b, out);
}

// round 16
// speedup vs baseline: 1.2770x; 1.2368x over previous
#include <cuda_runtime.h>
#include <cuda_bf16.h>
#include <math.h>

#define HW 192
#define NPIX (HW*HW)
#define NB 2
#define CIN 180
#define CP 360
#define KDIM 180
#define KC 12             // 12 chunks of k=16
#define MT_PROJ 24        // 384 padded M rows / 16
#define MT_FUSE 12        // 192 padded M rows / 16

#define GX 288
#define GY_PROJ 6
#define BLKS_B (GX*GY_PROJ)   // 1728 proj blocks per batch

#define BSTR 136          // B smem row stride in words (bank = 8t+g -> all 32)

// ---------------- scratch (static device globals; no allocation) ----------------
__device__ float g_xp[(size_t)NB*CP*NPIX];     // projected (pre-GN) features
__device__ float g_yf[(size_t)NB*CIN*NPIX];    // fused attention output
__device__ float g_part[NB*BLKS_B*4];
__device__ float g_affA[NB*CP];                // folded GN scale
__device__ float g_affB[NB*CP];                // folded GN bias
// A (=W) in bf16 hi/lo, m16n8k16 FRAGMENT order, one 32-bit word = (k, k+1) pair:
// frag = kc*MT + mt ; word index = frag*128 + lane*4 + j
// row = mt*16 + g + (j&1)*8 ; k = kc*16 + 2t + (j>>1)*8  (g=lane>>2, t=lane&3)
__device__ unsigned g_Ap_hi[KC*MT_PROJ*128], g_Ap_lo[KC*MT_PROJ*128];
__device__ unsigned g_Af_hi[KC*MT_FUSE*128], g_Af_lo[KC*MT_FUSE*128];

// ---------------- bf16 helpers ----------------
__device__ __forceinline__ unsigned pack2(float a, float b){
  __nv_bfloat162 h = __floats2bfloat162_rn(a, b);   // a -> low 16 bits (k even)
  return *(unsigned*)&h;
}
// split pair (a,b) into hi word + lo (residual) word
__device__ __forceinline__ void split2(float a, float b, unsigned& hi, unsigned& lo){
  __nv_bfloat16 ah = __float2bfloat16_rn(a);
  __nv_bfloat16 bh = __float2bfloat16_rn(b);
  float ra = a - __bfloat162float(ah);
  float rb = b - __bfloat162float(bh);
  __nv_bfloat162 h; h.x = ah; h.y = bh;
  hi = *(unsigned*)&h;
  lo = pack2(ra, rb);
}

__device__ __forceinline__ void mma_bf16(float* c, const uint4 a, const unsigned* b){
  asm volatile(
    "mma.sync.aligned.m16n8k16.row.col.f32.bf16.bf16.f32 "
    "{%0,%1,%2,%3}, {%4,%5,%6,%7}, {%8,%9}, {%0,%1,%2,%3};"
    : "+f"(c[0]), "+f"(c[1]), "+f"(c[2]), "+f"(c[3])
    : "r"(a.x), "r"(a.y), "r"(a.z), "r"(a.w), "r"(b[0]), "r"(b[1]));
}

// ---------------- weight pre-split into bf16 fragment layout ----------------
__global__ void split_w_kernel(const float* __restrict__ Wp, const float* __restrict__ Wf)
{
  int i = blockIdx.x*256 + threadIdx.x;
  const int NP = KC*MT_PROJ*128;
  if (i < NP){
    int j = i & 3, lane = (i >> 2) & 31, frag = i >> 7;
    int mt = frag % MT_PROJ, kc = frag / MT_PROJ;
    int g = lane >> 2, t = lane & 3;
    int row = mt*16 + g + (j & 1)*8;
    int k   = kc*16 + 2*t + (j >> 1)*8;
    float a0 = (row < CP && k   < KDIM) ? Wp[row*KDIM + k  ] : 0.f;
    float a1 = (row < CP && k+1 < KDIM) ? Wp[row*KDIM + k+1] : 0.f;
    unsigned hi, lo; split2(a0, a1, hi, lo);
    g_Ap_hi[i] = hi; g_Ap_lo[i] = lo;
  } else {
    int i2 = i - NP;
    if (i2 < KC*MT_FUSE*128){
      int j = i2 & 3, lane = (i2 >> 2) & 31, frag = i2 >> 7;
      int mt = frag % MT_FUSE, kc = frag / MT_FUSE;
      int g = lane >> 2, t = lane & 3;
      int row = mt*16 + g + (j & 1)*8;
      int k   = kc*16 + 2*t + (j >> 1)*8;
      float a0 = (row < CIN && k   < KDIM) ? Wf[row*KDIM + k  ] : 0.f;
      float a1 = (row < CIN && k+1 < KDIM) ? Wf[row*KDIM + k+1] : 0.f;
      unsigned hi, lo; split2(a0, a1, hi, lo);
      g_Af_hi[i2] = hi; g_Af_lo[i2] = lo;
    }
  }
}

// ---------------- BF16 3-term GEMM: C[b] = W (MxK) @ X[b] (KxNPIX) + bias -----
// BM=64, BN=128, BK=16. 256 threads, 2x4 warp grid, 32x32 warp tiles.
// m16n8k16 HMMA: C += Ah*Bh + Ah*Bl + Al*Bh   (hi+lo bf16 ~ 17 mantissa bits).
// A fragments straight from global (fragment-ordered, L2-hot).
// B split into k-pair-major smem words, stride 136 (conflict-free).
template<bool PROJ>
__global__ void __launch_bounds__(256) gemm_bf16(const float* __restrict__ Xin,
                                                 const float* __restrict__ bias,
                                                 float* __restrict__ Cout)
{
  constexpr int MT = PROJ ? MT_PROJ : MT_FUSE;
  constexpr int M  = PROJ ? CP : CIN;
  const uint4* Afh = (const uint4*)(PROJ ? g_Ap_hi : g_Af_hi);
  const uint4* Afl = (const uint4*)(PROJ ? g_Ap_lo : g_Af_lo);

  __shared__ unsigned Bs_hi[8*BSTR], Bs_lo[8*BSTR];   // [kpair][n] words
  __shared__ float red[1024];

  const int b = blockIdx.z;
  const float* X = PROJ ? (Xin + (size_t)b*KDIM*NPIX)
                        : (g_yf + (size_t)b*CIN*NPIX);
  float* C = PROJ ? (g_xp + (size_t)b*CP*NPIX)
                  : (Cout + (size_t)b*CIN*NPIX);

  const int tid  = threadIdx.x;
  const int lane = tid & 31, warp = tid >> 5;
  const int wm = warp >> 2, wn = warp & 3;          // 2 x 4 warp grid
  const int g  = lane >> 2, t = lane & 3;
  const int m0t = blockIdx.y*4;                     // first m-tile (64 rows = 4 tiles)
  const int n0 = blockIdx.x*128;

  // B loader coords: kp = which k-pair (0..7), n4 = which 4-col group
  const int kp = tid >> 5, n4 = tid & 31;

  float Cf[2][4][4];
#pragma unroll
  for (int mi=0;mi<2;mi++)
#pragma unroll
    for (int ni=0;ni<4;ni++)
#pragma unroll
      for (int e=0;e<4;e++) Cf[mi][ni][e] = 0.f;

  // prefetch chunk 0 (raw fp32, rows k=2kp and 2kp+1)
  float4 v0, v1;
  {
    int k0 = 2*kp, k1 = 2*kp + 1;
    v0 = (k0 < KDIM) ? *(const float4*)(X + (size_t)k0*NPIX + n0 + n4*4) : make_float4(0,0,0,0);
    v1 = (k1 < KDIM) ? *(const float4*)(X + (size_t)k1*NPIX + n0 + n4*4) : make_float4(0,0,0,0);
  }

  for (int ki = 0; ki < KC; ki++){
    // split + store current chunk: word = (k even, k odd) bf16 pair
    {
      uint4 hw, lw;
      split2(v0.x, v1.x, hw.x, lw.x);
      split2(v0.y, v1.y, hw.y, lw.y);
      split2(v0.z, v1.z, hw.z, lw.z);
      split2(v0.w, v1.w, hw.w, lw.w);
      *(uint4*)(Bs_hi + kp*BSTR + n4*4) = hw;
      *(uint4*)(Bs_lo + kp*BSTR + n4*4) = lw;
    }
    __syncthreads();
    // prefetch next chunk
    if (ki < KC-1){
      int k0 = (ki+1)*16 + 2*kp, k1 = k0 + 1;
      v0 = (k0 < KDIM) ? *(const float4*)(X + (size_t)k0*NPIX + n0 + n4*4) : make_float4(0,0,0,0);
      v1 = (k1 < KDIM) ? *(const float4*)(X + (size_t)k1*NPIX + n0 + n4*4) : make_float4(0,0,0,0);
    }
    // compute on current chunk: one k16 step
    {
      uint4 Ah[2], Al[2];
#pragma unroll
      for (int mi=0;mi<2;mi++){
        int mt = m0t + wm*2 + mi;
        int fo = (ki*MT + mt)*32 + lane;
        Ah[mi] = Afh[fo];
        Al[mi] = Afl[fo];
      }
      unsigned Bh[4][2], Bl[4][2];
#pragma unroll
      for (int ni=0;ni<4;ni++){
        int c = wn*32 + ni*8 + g;
        Bh[ni][0] = Bs_hi[ t   *BSTR + c];   // k rows 2t, 2t+1
        Bh[ni][1] = Bs_hi[(t+4)*BSTR + c];   // k rows 2t+8, 2t+9
        Bl[ni][0] = Bs_lo[ t   *BSTR + c];
        Bl[ni][1] = Bs_lo[(t+4)*BSTR + c];
      }
#pragma unroll
      for (int mi=0;mi<2;mi++)
#pragma unroll
        for (int ni=0;ni<4;ni++){
          mma_bf16(Cf[mi][ni], Ah[mi], Bh[ni]);
          mma_bf16(Cf[mi][ni], Ah[mi], Bl[ni]);
          mma_bf16(Cf[mi][ni], Al[mi], Bh[ni]);
        }
    }
    __syncthreads();
  }

  // --- epilogue: bias add, store, GN partial sums (PROJ) ---
  float st0=0.f, st1=0.f, st2=0.f, st3=0.f;
#pragma unroll
  for (int mi=0;mi<2;mi++){
#pragma unroll
    for (int rs=0;rs<2;rs++){
      int gm = m0t*16 + wm*32 + mi*16 + g + rs*8;
      if (gm < M){
        float bb = bias[gm];
        float* crow = C + (size_t)gm*NPIX + n0 + wn*32;
        float s = 0.f, q = 0.f;
#pragma unroll
        for (int ni=0;ni<4;ni++){
          float u0 = Cf[mi][ni][rs*2+0] + bb;
          float u1 = Cf[mi][ni][rs*2+1] + bb;
          *(float2*)(crow + ni*8 + 2*t) = make_float2(u0, u1);
          if (PROJ){ s += u0 + u1; q = fmaf(u0,u0,fmaf(u1,u1,q)); }
        }
        if (PROJ){
          if (gm < CIN){ st0 += s; st1 += q; } else { st2 += s; st3 += q; }
        }
      }
    }
  }
  if (PROJ){
    __syncthreads();
    red[tid] = st0; red[256+tid] = st1; red[512+tid] = st2; red[768+tid] = st3;
    __syncthreads();
    for (int o=128;o;o>>=1){
      if (tid < o){
        red[tid]     += red[tid+o];
        red[256+tid] += red[256+tid+o];
        red[512+tid] += red[512+tid+o];
        red[768+tid] += red[768+tid+o];
      }
      __syncthreads();
    }
    if (tid == 0){
      int bid = (blockIdx.z*gridDim.y + blockIdx.y)*gridDim.x + blockIdx.x;
      g_part[bid*4+0]=red[0];   g_part[bid*4+1]=red[256];
      g_part[bid*4+2]=red[512]; g_part[bid*4+3]=red[768];
    }
  }
}

// ---------------- GN stats + affine fold (single block, deterministic) ----------------
__global__ void stats_affine_kernel(const float* __restrict__ gamma,
                                    const float* __restrict__ beta)
{
  __shared__ float ss[256], sq[256];
  __shared__ float stats[8];
  const int tid = threadIdx.x;
  for (int bg = 0; bg < 4; bg++){
    const int b = bg >> 1, gg = bg & 1;
    float s = 0.f, q = 0.f;
    for (int i = tid; i < BLKS_B; i += 256){
      int bid = b*BLKS_B + i;
      s += g_part[bid*4 + gg*2];
      q += g_part[bid*4 + gg*2 + 1];
    }
    ss[tid] = s; sq[tid] = q;
    __syncthreads();
    for (int o=128;o;o>>=1){
      if (tid < o){ ss[tid]+=ss[tid+o]; sq[tid]+=sq[tid+o]; }
      __syncthreads();
    }
    if (tid == 0){
      const float N = 180.f * (float)NPIX;
      float mu  = ss[0] / N;
      float var = sq[0] / N - mu*mu;
      stats[bg*2]   = mu;
      stats[bg*2+1] = rsqrtf(var + 1e-5f);
    }
    __syncthreads();
  }
  for (int i = tid; i < NB*CP; i += 256){
    int c = i % CP, b = i / CP;
    int gg = (c >= CIN) ? 1 : 0;
    float mu   = stats[(b*2+gg)*2];
    float istd = stats[(b*2+gg)*2+1];
    float a = istd * gamma[c];
    g_affA[i] = a;
    g_affB[i] = fmaf(-mu, a, beta[c]);
  }
}

// ---------------- windowed attention, one block per (window, head) ----------------
// The reference's "global token" path is an exact identity (softmax of selected
// rows == selected rows of softmax), so attn maps and outputs are plain local
// window attention. Writes softmax rows to attn_out (= d_out slice) and
// scale_w * (attn@V) directly into g_yf.
template<int WS, int HE, int CHN, int NCH>
__global__ void __launch_bounds__(256) attn_kernel(int branch,
                                                   const float* __restrict__ swp,
                                                   float* __restrict__ attn_out)
{
  constexpr int T    = WS*WS;
  constexpr int NWIN = HW/WS;
  constexpr int TPAD = T + 4;
  constexpr int CPC  = CHN / NCH;
  static_assert(CHN % NCH == 0, "chunking");

  extern __shared__ float sm[];
  float* qT = sm;                  // [CHN][T]  (already *he^-0.5, GN applied)
  float* vT = sm + CHN*T;          // [CHN][T]
  float* Am = sm + 2*CHN*T;        // [T][TPAD]
  __shared__ int pixs[T];

  const int w  = blockIdx.x;
  const int hh = blockIdx.y;
  const int b  = w / (NWIN*NWIN);
  const int r  = w - b*NWIN*NWIN;
  const int ih = r / NWIN, iw = r - ih*NWIN;
  const int tid = threadIdx.x;

  if (tid < T){
    int ty = tid / WS, tx = tid - ty*WS;
    int hs  = (ih*WS + ty - WS/2 + HW) % HW;   // roll(+ws/2) on H
    int wsr = (iw*WS + tx + WS/2) % HW;        // roll(-ws/2) on W
    pixs[tid] = hs*HW + wsr;                   // same pixel for gather & scatter
  }
  __syncthreads();

  const float qsc = (HE==2) ? 0.70710678f : (HE==4) ? 0.5f : 0.40824829f;
  const float* xp = g_xp + (size_t)b*CP*NPIX;
  const float* aA = g_affA + b*CP;
  const float* aB = g_affB + b*CP;
  const int cb = branch*120 + hh;             // q channel = cb + cc*HE ; v = +60

  // ---- load + GN-normalize Q,V ----
  for (int idx = tid; idx < CHN*T; idx += 256){
    int cc = idx / T, t = idx - cc*T;
    int pix = pixs[t];
    int Cq = cb + cc*HE;
    int Cv = Cq + 60;
    float q = xp[(size_t)Cq*NPIX + pix];
    float v = xp[(size_t)Cv*NPIX + pix];
    qT[idx] = fmaf(q, aA[Cq], aB[Cq]) * qsc;
    vT[idx] = fmaf(v, aA[Cv], aB[Cv]);
  }
  __syncthreads();

  // ---- S = (q_l)(q_l)^T  (4x4 register tiles) ----
  constexpr int NT4 = T/4;
  for (int tile = tid; tile < NT4*NT4; tile += 256){
    int tt = tile / NT4, ssi = tile - tt*NT4;
    int t0 = tt*4, s0 = ssi*4;
    float accv[4][4];
#pragma unroll
    for (int i=0;i<4;i++)
#pragma unroll
      for (int j=0;j<4;j++) accv[i][j] = 0.f;
#pragma unroll
    for (int c=0;c<CHN;c++){
      float4 qa = *(const float4*)(qT + c*T + t0);
      float4 qb = *(const float4*)(qT + c*T + s0);
      float qav[4] = {qa.x,qa.y,qa.z,qa.w};
      float qbv[4] = {qb.x,qb.y,qb.z,qb.w};
#pragma unroll
      for (int i=0;i<4;i++)
#pragma unroll
        for (int j=0;j<4;j++)
          accv[i][j] = fmaf(qav[i], qbv[j], accv[i][j]);
    }
#pragma unroll
    for (int i=0;i<4;i++)
      *(float4*)(Am + (t0+i)*TPAD + s0) =
          make_float4(accv[i][0],accv[i][1],accv[i][2],accv[i][3]);
  }
  __syncthreads();

  // ---- softmax per row + write attn map to global ----
  const int warp = tid >> 5, lane = tid & 31;
  for (int t = warp; t < T; t += 8){
    float* arow = Am + t*TPAD;
    float mx = -1e30f;
    for (int s=lane; s<T; s+=32) mx = fmaxf(mx, arow[s]);
#pragma unroll
    for (int o=16;o;o>>=1) mx = fmaxf(mx, __shfl_xor_sync(0xffffffffu, mx, o));
    float sum = 0.f;
    for (int s=lane; s<T; s+=32){ float e = __expf(arow[s]-mx); arow[s]=e; sum+=e; }
#pragma unroll
    for (int o=16;o;o>>=1) sum += __shfl_xor_sync(0xffffffffu, sum, o);
    float inv = 1.f/sum;
    float* grow = attn_out + (((size_t)w*HE + hh)*T + t)*T;
    for (int s=lane; s<T; s+=32){ float p = arow[s]*inv; arow[s]=p; grow[s]=p; }
  }
  __syncthreads();

  // ---- O = attn @ V, scatter scaled output into y_fused ----
  float sw = swp[branch];
  if (tid < T*NCH){
    int chunk = tid / T, t = tid - chunk*T;
    const float* arow = Am + t*TPAD;
    const float* vb = vT + chunk*CPC*T;
    float o[CPC];
#pragma unroll
    for (int c=0;c<CPC;c++) o[c] = 0.f;
    for (int s=0; s<T; s+=4){
      float4 a4 = *(const float4*)(arow + s);
#pragma unroll
      for (int c=0;c<CPC;c++){
        float4 v4 = *(const float4*)(vb + c*T + s);
        o[c] = fmaf(a4.x, v4.x, o[c]);
        o[c] = fmaf(a4.y, v4.y, o[c]);
        o[c] = fmaf(a4.z, v4.z, o[c]);
        o[c] = fmaf(a4.w, v4.w, o[c]);
      }
    }
    int pix = pixs[t];
    float* yb = g_yf + (size_t)b*CIN*NPIX;
#pragma unroll
    for (int c=0;c<CPC;c++){
      int cc = chunk*CPC + c;
      int Cy = branch*60 + cc*HE + hh;
      yb[(size_t)Cy*NPIX + pix] = sw * o[c];
    }
  }
}

// ---------------- launcher ----------------
extern "C" void kernel_launch(void* const* d_in, const int* in_sizes, int n_in,
                              void* d_out, int out_size)
{
  const float* x        = (const float*)d_in[0];
  const float* proj_w   = (const float*)d_in[1];
  const float* proj_b   = (const float*)d_in[2];
  const float* gn_gamma = (const float*)d_in[3];
  const float* gn_beta  = (const float*)d_in[4];
  // d_in[5] token_scores: provably unused (global path is identity)
  const float* scale_w  = (const float*)d_in[6];
  const float* fuse_w   = (const float*)d_in[7];
  const float* fuse_b   = (const float*)d_in[8];
  float* out = (float*)d_out;

  // d_out layout: y | atn0 | atn1 | atn2
  const size_t OFF_A0 = (size_t)NB*CIN*NPIX;
  const size_t OFF_A1 = OFF_A0 + (size_t)NB*48*48*2*16*16;
  const size_t OFF_A2 = OFF_A1 + (size_t)NB*24*24*4*64*64;

  const int SM0 = (2*30*16  + 16*20)  * 4;   //  5,120 B
  const int SM1 = (2*15*64  + 64*68)  * 4;   // 25,088 B
  const int SM2 = (2*10*144 + 144*148)* 4;   // 96,768 B
  cudaFuncSetAttribute(attn_kernel<12,6,10,1>,
                       cudaFuncAttributeMaxDynamicSharedMemorySize, SM2);

  // 0) pre-split weights into bf16 hi/lo fragment layout
  int prep_n = KC*MT_PROJ*128 + KC*MT_FUSE*128;       // 55296 words
  split_w_kernel<<<(prep_n + 255)/256, 256>>>(proj_w, fuse_w);
  // 1) proj GEMM (bf16 tensor core, 3-term) + GN partials
  gemm_bf16<true><<<dim3(GX, GY_PROJ, NB), 256>>>(x, proj_b, nullptr);
  // 2) GN stats + affine fold
  stats_affine_kernel<<<1, 256>>>(gn_gamma, gn_beta);
  // 3) three attention branches
  attn_kernel<4, 2, 30, 15><<<dim3(NB*48*48, 2), 256, SM0>>>(0, scale_w, out + OFF_A0);
  attn_kernel<8, 4, 15,  3><<<dim3(NB*24*24, 4), 256, SM1>>>(1, scale_w, out + OFF_A1);
  attn_kernel<12,6, 10,  1><<<dim3(NB*16*16, 6), 256, SM2>>>(2, scale_w, out + OFF_A2);
  // 4) fuse GEMM (bf16 tensor core, 3-term) -> y
  gemm_bf16<false><<<dim3(GX, 3, NB), 256>>>(nullptr, fuse_b, out);
}